// round 6
// baseline (speedup 1.0000x reference)
#include <cuda_runtime.h>
#include <math.h>

// ---------------------------------------------------------------------------
// YoloLoss: predictions (N,7,7,90) f32, target (N,7,7,85) f32 -> 4 scalars
// Warp-autonomous work-stealing; 128-thread blocks x 1520 (10/SM, 40 warps/SM).
// objv (per-cell obj) is software-pipelined across groups so its dependent
// load is hidden under Phase B + the steal atomic.
// ---------------------------------------------------------------------------

#define PRED_C 90
#define TGT_C  85

static constexpr int THREADS = 128;
static constexpr int WARPS   = THREADS / 32;
static constexpr int NBLOCKS = 1520;    // 10 blocks/SM on 152 SMs
static constexpr int GRP     = 32;      // cells per warp-group

__device__ float    g_partials[NBLOCKS * 4];
__device__ unsigned g_work  = 0;   // work-stealing counter
__device__ unsigned g_count = 0;   // completion counter

__device__ __forceinline__ float iou_cxcywh(float ax, float ay, float aw, float ah,
                                            float bx, float by, float bw, float bh) {
    float ax1 = ax - aw * 0.5f, ay1 = ay - ah * 0.5f;
    float ax2 = ax + aw * 0.5f, ay2 = ay + ah * 0.5f;
    float bx1 = bx - bw * 0.5f, by1 = by - bh * 0.5f;
    float bx2 = bx + bw * 0.5f, by2 = by + bh * 0.5f;
    float iw = fmaxf(fminf(ax2, bx2) - fmaxf(ax1, bx1), 0.0f);
    float ih = fmaxf(fminf(ay2, by2) - fmaxf(ay1, by1), 0.0f);
    float inter  = iw * ih;
    float area_a = (ax2 - ax1) * (ay2 - ay1);
    float area_b = (bx2 - bx1) * (by2 - by1);
    return inter / (area_a + area_b - inter);
}

__device__ __forceinline__ float sgnsqrt(float x) {
    float s = (x > 0.0f) ? 1.0f : ((x < 0.0f) ? -1.0f : 0.0f);
    return s * sqrtf(fabsf(x) + 1e-6f);
}

__global__ __launch_bounds__(THREADS, 10)
void yolo_loss_fused(const float* __restrict__ P, const float* __restrict__ T,
                     float* __restrict__ out, int ncells) {
    // Per-warp stash. Stride 11 / 5 (odd) -> conflict-free Phase B reads.
    __shared__ float boxP[WARPS][GRP][11];   // p80,b2x,b2y,b2w,b2h,p85,b1x..b1h
    __shared__ float boxT[WARPS][GRP][5];    // obj,tbx,tby,tbw,tbh
    __shared__ float  red[4][WARPS];
    __shared__ double dred[4][WARPS];
    __shared__ int    s_last;

    const unsigned FULL = 0xffffffffu;
    const int tid  = threadIdx.x;
    const int lane = tid & 31;
    const int wrp  = tid >> 5;

    const int ngroups = (ncells + GRP - 1) / GRP;

    float aC = 0.0f, aO = 0.0f, aN = 0.0f;
    float aL0 = 0.0f, aL1 = 0.0f, aL2 = 0.0f;

    const unsigned li = (unsigned)(lane - 16);   // chunk-2 stash index

    // ---- Steal first group and start its objv load immediately ----
    int cur;
    if (lane == 0) cur = (int)atomicAdd(&g_work, 1u);
    cur = __shfl_sync(FULL, cur, 0);

    float objv = 0.0f;
    if (cur < ngroups) {
        int oc = min(cur * GRP + lane, ncells - 1);
        objv = T[(size_t)oc * TGT_C + 80];
    }

    while (cur < ngroups) {
        int nxt;
        if (lane == 0) nxt = (int)atomicAdd(&g_work, 1u);   // hidden under work
        nxt = __shfl_sync(FULL, nxt, 0);

        const int cbase = cur * GRP;

        if (cbase + GRP <= ncells) {
            // ---------------- full group: clean pipelined loop ----------------
            #pragma unroll 4
            for (int c = 0; c < GRP; c++) {
                const float* p = P + (size_t)(cbase + c) * PRED_C;
                const float* t = T + (size_t)(cbase + c) * TGT_C;

                float p0 = p[lane];
                float p1 = p[32 + lane];
                float p2 = (lane < PRED_C - 64) ? p[64 + lane] : 0.0f;
                float t0 = t[lane];
                float t1 = t[32 + lane];
                float t2 = (lane < TGT_C - 64) ? t[64 + lane] : 0.0f;

                float obj = __shfl_sync(FULL, objv, c);   // resident register

                float d0 = fmaf(p0, obj, -t0);  aL0 = fmaf(d0, d0, aL0);
                float d1 = fmaf(p1, obj, -t1);  aL1 = fmaf(d1, d1, aL1);
                if (lane < 16) {
                    float d2 = fmaf(p2, obj, -t2);  aL2 = fmaf(d2, d2, aL2);
                }

                if (li < 10u) boxP[wrp][c][li] = p2;   // preds[80..89]
                if (li < 5u)  boxT[wrp][c][li] = t2;   // target[80..84]
            }
        } else {
            // ---------------- ragged tail (not taken for 401408) --------------
            for (int c = 0; c < GRP; c++) {
                int cell = cbase + c;
                if (cell >= ncells) break;
                const float* p = P + (size_t)cell * PRED_C;
                const float* t = T + (size_t)cell * TGT_C;
                float p0 = p[lane];
                float p1 = p[32 + lane];
                float p2 = (lane < PRED_C - 64) ? p[64 + lane] : 0.0f;
                float t0 = t[lane];
                float t1 = t[32 + lane];
                float t2 = (lane < TGT_C - 64) ? t[64 + lane] : 0.0f;
                float obj = __shfl_sync(FULL, objv, c);
                float d0 = fmaf(p0, obj, -t0);  aL0 = fmaf(d0, d0, aL0);
                float d1 = fmaf(p1, obj, -t1);  aL1 = fmaf(d1, d1, aL1);
                if (lane < 16) {
                    float d2 = fmaf(p2, obj, -t2);  aL2 = fmaf(d2, d2, aL2);
                }
                if (li < 10u) boxP[wrp][c][li] = p2;
                if (li < 5u)  boxT[wrp][c][li] = t2;
            }
        }

        // ---- Prefetch next group's objv: overlaps Phase B + loop latency ----
        float objv_next = 0.0f;
        if (nxt < ngroups) {
            int oc = min(nxt * GRP + lane, ncells - 1);
            objv_next = T[(size_t)oc * TGT_C + 80];
        }
        __syncwarp();

        // ---- Phase B: box math, one cell per lane ----
        if (cbase + lane < ncells) {
            const float* bp = boxP[wrp][lane];
            const float* bt = boxT[wrp][lane];
            float p80 = bp[0];
            float b2x = bp[1], b2y = bp[2], b2w = bp[3], b2h = bp[4];
            float p85 = bp[5];
            float b1x = bp[6], b1y = bp[7], b1w = bp[8], b1h = bp[9];
            float obj = bt[0];
            float tbx = bt[1], tby = bt[2], tbw = bt[3], tbh = bt[4];

            float iou1 = iou_cxcywh(b1x, b1y, b1w, b1h, tbx, tby, tbw, tbh);
            float iou2 = iou_cxcywh(b2x, b2y, b2w, b2h, tbx, tby, tbw, tbh);
            bool pick2 = iou2 > iou1;   // numpy argmax: first max wins ties

            float bx = pick2 ? b2x : b1x;
            float bw = pick2 ? b2w : b1w;
            float bh = pick2 ? b2h : b1h;
            float op = pick2 ? p80 : p85;

            // pred_boxes = obj * chosen box; center loss uses cx only ([..., :-3])
            float dc = fmaf(obj, bx, -tbx);
            aC = fmaf(dc, dc, aC);
            float dw = sgnsqrt(obj * bw) - sqrtf(tbw);
            aC = fmaf(dw, dw, aC);
            float dh = sgnsqrt(obj * bh) - sqrtf(tbh);
            aC = fmaf(dh, dh, aC);

            float e1 = fmaf(obj, op, -obj);
            aO = fmaf(e1, e1, aO);
            float e2 = fmaf(1.0f - obj, op, -obj);
            aN = fmaf(e2, e2, aN);
        }
        __syncwarp();   // stash reuse next group

        cur = nxt;
        objv = objv_next;
    }

    float aL = (aL0 + aL1) + aL2;

    // ---- Block reduction ----
    #pragma unroll
    for (int off = 16; off > 0; off >>= 1) {
        aC += __shfl_xor_sync(FULL, aC, off);
        aO += __shfl_xor_sync(FULL, aO, off);
        aN += __shfl_xor_sync(FULL, aN, off);
        aL += __shfl_xor_sync(FULL, aL, off);
    }
    if (lane == 0) {
        red[0][wrp] = aC; red[1][wrp] = aO; red[2][wrp] = aN; red[3][wrp] = aL;
    }
    __syncthreads();
    if (tid == 0) {
        float s0 = 0, s1 = 0, s2 = 0, s3 = 0;
        #pragma unroll
        for (int w = 0; w < WARPS; w++) {
            s0 += red[0][w]; s1 += red[1][w]; s2 += red[2][w]; s3 += red[3][w];
        }
        g_partials[blockIdx.x * 4 + 0] = s0;
        g_partials[blockIdx.x * 4 + 1] = s1;
        g_partials[blockIdx.x * 4 + 2] = s2;
        g_partials[blockIdx.x * 4 + 3] = s3;
        __threadfence();
        unsigned prev = atomicAdd(&g_count, 1u);
        s_last = (prev == gridDim.x - 1) ? 1 : 0;
    }
    __syncthreads();

    // ---- Last block finalizes & resets counters for graph replay ----
    if (s_last) {
        double v0 = 0, v1 = 0, v2 = 0, v3 = 0;
        for (int b = tid; b < (int)gridDim.x; b += THREADS) {
            v0 += (double)__ldcg(&g_partials[b * 4 + 0]);
            v1 += (double)__ldcg(&g_partials[b * 4 + 1]);
            v2 += (double)__ldcg(&g_partials[b * 4 + 2]);
            v3 += (double)__ldcg(&g_partials[b * 4 + 3]);
        }
        #pragma unroll
        for (int off = 16; off > 0; off >>= 1) {
            v0 += __shfl_xor_sync(FULL, v0, off);
            v1 += __shfl_xor_sync(FULL, v1, off);
            v2 += __shfl_xor_sync(FULL, v2, off);
            v3 += __shfl_xor_sync(FULL, v3, off);
        }
        if (lane == 0) {
            dred[0][wrp] = v0; dred[1][wrp] = v1; dred[2][wrp] = v2; dred[3][wrp] = v3;
        }
        __syncthreads();
        if (tid == 0) {
            double c = 0, o = 0, n = 0, cl = 0;
            #pragma unroll
            for (int w = 0; w < WARPS; w++) {
                c += dred[0][w]; o += dred[1][w]; n += dred[2][w]; cl += dred[3][w];
            }
            out[0] = (float)(c * 5.0);   // coords (LAMBDA_COORDS)
            out[1] = (float)o;           // obj
            out[2] = (float)(n * 0.5);   // noobj (LAMBDA_NOOBJ)
            out[3] = (float)cl;          // classes
            atomicExch(&g_work, 0u);     // reset for next graph replay
            atomicExch(&g_count, 0u);
        }
    }
}

extern "C" void kernel_launch(void* const* d_in, const int* in_sizes, int n_in,
                              void* d_out, int out_size) {
    const float* P = (const float*)d_in[0];   // predictions
    const float* T = (const float*)d_in[1];   // target
    float* out = (float*)d_out;

    int ncells = in_sizes[0] / PRED_C;        // 8192*7*7 = 401408

    yolo_loss_fused<<<NBLOCKS, THREADS>>>(P, T, out, ncells);
}

// round 7
// speedup vs baseline: 1.4882x; 1.4882x over previous
#include <cuda_runtime.h>
#include <math.h>
#include <stdint.h>

// ---------------------------------------------------------------------------
// YoloLoss: predictions (N,7,7,90) f32, target (N,7,7,85) f32 -> 4 scalars
// cp.async.bulk double-buffered smem pipeline:
//   - 64-cell tiles: preds 23040 B + target 21760 B per tile (16B aligned)
//   - mbarrier expect_tx producer (tid 0), all-thread consumer, 2 buffers
//   - compute: 4 threads/cell class loss + 1 thread/cell box/IoU math from smem
//   - last-block-done fused finalize (self-resets for graph replay)
// ---------------------------------------------------------------------------

#define PRED_C 90
#define TGT_C  85

static constexpr int THREADS   = 256;
static constexpr int WARPS     = THREADS / 32;
static constexpr int NBLOCKS   = 304;               // 2 per SM (152 SMs)
static constexpr int TILE      = 64;                // cells per tile
static constexpr int SP_FLOATS = TILE * PRED_C;     // 5760
static constexpr int ST_FLOATS = TILE * TGT_C;      // 5440
static constexpr int SP_BYTES  = SP_FLOATS * 4;     // 23040
static constexpr int ST_BYTES  = ST_FLOATS * 4;     // 21760
static constexpr int TILE_BYTES = SP_BYTES + ST_BYTES;   // 44800
static constexpr int DYN_SMEM  = 2 * TILE_BYTES + 64;    // + barrier space

__device__ float    g_partials[NBLOCKS * 4];
__device__ unsigned g_count = 0;

// ---- PTX helpers ----
__device__ __forceinline__ uint32_t smem_u32(const void* p) {
    return (uint32_t)__cvta_generic_to_shared(p);
}
#define MBAR_INIT(addr, cnt) \
    asm volatile("mbarrier.init.shared.b64 [%0], %1;" :: "r"(addr), "r"(cnt) : "memory")
#define MBAR_EXPECT_TX(addr, bytes) \
    asm volatile("mbarrier.arrive.expect_tx.shared.b64 _, [%0], %1;" :: "r"(addr), "r"(bytes) : "memory")
#define MBAR_ARRIVE(addr) \
    asm volatile("mbarrier.arrive.shared.b64 _, [%0];" :: "r"(addr) : "memory")
#define MBAR_WAIT_PARITY(addr, ph) do {                                        \
    asm volatile("{\n\t.reg .pred P1;\n"                                       \
                 "WL_%=:\n\t"                                                  \
                 "mbarrier.try_wait.parity.acquire.cta.shared::cta.b64 P1, [%0], %1;\n\t" \
                 "@!P1 bra WL_%=;\n\t}"                                        \
                 :: "r"(addr), "r"(ph) : "memory");                            \
} while (0)
#define BULK_G2S(dst_smem, src_gmem, bytes, mbar) \
    asm volatile("cp.async.bulk.shared::cluster.global.mbarrier::complete_tx::bytes " \
                 "[%0], [%1], %2, [%3];"                                       \
                 :: "r"(dst_smem), "l"(src_gmem), "r"(bytes), "r"(mbar) : "memory")

__device__ __forceinline__ float iou_cxcywh(float ax, float ay, float aw, float ah,
                                            float bx, float by, float bw, float bh) {
    float ax1 = ax - aw * 0.5f, ay1 = ay - ah * 0.5f;
    float ax2 = ax + aw * 0.5f, ay2 = ay + ah * 0.5f;
    float bx1 = bx - bw * 0.5f, by1 = by - bh * 0.5f;
    float bx2 = bx + bw * 0.5f, by2 = by + bh * 0.5f;
    float iw = fmaxf(fminf(ax2, bx2) - fmaxf(ax1, bx1), 0.0f);
    float ih = fmaxf(fminf(ay2, by2) - fmaxf(ay1, by1), 0.0f);
    float inter  = iw * ih;
    float area_a = (ax2 - ax1) * (ay2 - ay1);
    float area_b = (bx2 - bx1) * (by2 - by1);
    return inter / (area_a + area_b - inter);
}

__device__ __forceinline__ float sgnsqrt(float x) {
    float s = (x > 0.0f) ? 1.0f : ((x < 0.0f) ? -1.0f : 0.0f);
    return s * sqrtf(fabsf(x) + 1e-6f);
}

// Full per-cell box/obj/noobj math (reference semantics).
__device__ __forceinline__ void cell_box_math(
    const float* __restrict__ pb,   // preds[80..89]
    const float* __restrict__ tb,   // target[80..84]
    float& aC, float& aO, float& aN) {
    float p80 = pb[0];
    float b2x = pb[1], b2y = pb[2], b2w = pb[3], b2h = pb[4];
    float p85 = pb[5];
    float b1x = pb[6], b1y = pb[7], b1w = pb[8], b1h = pb[9];
    float obj = tb[0];
    float tbx = tb[1], tby = tb[2], tbw = tb[3], tbh = tb[4];

    float iou1 = iou_cxcywh(b1x, b1y, b1w, b1h, tbx, tby, tbw, tbh);
    float iou2 = iou_cxcywh(b2x, b2y, b2w, b2h, tbx, tby, tbw, tbh);
    bool pick2 = iou2 > iou1;   // numpy argmax: first max wins ties

    float bx = pick2 ? b2x : b1x;
    float bw = pick2 ? b2w : b1w;
    float bh = pick2 ? b2h : b1h;
    float op = pick2 ? p80 : p85;

    // pred_boxes = obj * chosen box; center loss uses cx only ([..., :-3])
    float dc = fmaf(obj, bx, -tbx);
    aC = fmaf(dc, dc, aC);
    float dw = sgnsqrt(obj * bw) - sqrtf(tbw);
    aC = fmaf(dw, dw, aC);
    float dh = sgnsqrt(obj * bh) - sqrtf(tbh);
    aC = fmaf(dh, dh, aC);

    float e1 = fmaf(obj, op, -obj);
    aO = fmaf(e1, e1, aO);
    float e2 = fmaf(1.0f - obj, op, -obj);
    aN = fmaf(e2, e2, aN);
}

__global__ __launch_bounds__(THREADS)
void yolo_loss_tma(const float* __restrict__ P, const float* __restrict__ T,
                   float* __restrict__ out, int ncells) {
    extern __shared__ __align__(16) unsigned char dyn[];
    float* spb[2];  float* stb[2];
    spb[0] = (float*)dyn;
    stb[0] = spb[0] + SP_FLOATS;
    spb[1] = stb[0] + ST_FLOATS;
    stb[1] = spb[1] + SP_FLOATS;
    uint64_t* bars = (uint64_t*)(dyn + 2 * TILE_BYTES);   // [0..1]=full, [2..3]=empty
    uint32_t full_a[2]  = { smem_u32(&bars[0]), smem_u32(&bars[1]) };
    uint32_t empty_a[2] = { smem_u32(&bars[2]), smem_u32(&bars[3]) };

    __shared__ float  red[4][WARPS];
    __shared__ double dred[4][WARPS];
    __shared__ int    s_last;

    const unsigned FULL = 0xffffffffu;
    const int tid  = threadIdx.x;
    const int lane = tid & 31;
    const int wrp  = tid >> 5;

    const int ntiles = ncells / TILE;
    const int rem    = ncells - ntiles * TILE;
    // tiles owned by this block: tl = blockIdx.x + i*gridDim.x
    const int nmine = ((int)blockIdx.x < ntiles)
                    ? (ntiles - 1 - (int)blockIdx.x) / (int)gridDim.x + 1 : 0;

    if (tid == 0) {
        MBAR_INIT(full_a[0], 1);
        MBAR_INIT(full_a[1], 1);
        MBAR_INIT(empty_a[0], THREADS);
        MBAR_INIT(empty_a[1], THREADS);
    }
    __syncthreads();

    // ---- Prologue: issue up to 2 tiles ----
    if (tid == 0) {
        int pre = nmine < 2 ? nmine : 2;
        for (int i = 0; i < pre; i++) {
            int tl = blockIdx.x + i * gridDim.x;
            MBAR_EXPECT_TX(full_a[i], TILE_BYTES);
            BULK_G2S(smem_u32(spb[i]), P + (size_t)tl * SP_FLOATS, SP_BYTES, full_a[i]);
            BULK_G2S(smem_u32(stb[i]), T + (size_t)tl * ST_FLOATS, ST_BYTES, full_a[i]);
        }
    }

    float aC = 0.0f, aO = 0.0f, aN = 0.0f, aL = 0.0f;
    const int cc = tid >> 2;          // cell for class loss (4 threads/cell)
    const int k0 = (tid & 3) * 20;    // class sub-range start

    for (int it = 0; it < nmine; it++) {
        const int b  = it & 1;
        const int ph = (it >> 1) & 1;
        MBAR_WAIT_PARITY(full_a[b], ph);

        const float* sp = spb[b];
        const float* st = stb[b];

        // ---- class loss: 4 threads per cell, 20 classes each ----
        {
            const float* pc = sp + cc * PRED_C + k0;
            const float* tc = st + cc * TGT_C;
            float obj = tc[80];
            const float* tk = tc + k0;
            float l0 = 0.0f, l1 = 0.0f;
            #pragma unroll
            for (int j = 0; j < 20; j += 2) {
                float d0 = fmaf(pc[j],     obj, -tk[j]);     l0 = fmaf(d0, d0, l0);
                float d1 = fmaf(pc[j + 1], obj, -tk[j + 1]); l1 = fmaf(d1, d1, l1);
            }
            aL += l0 + l1;
        }

        // ---- box math: one thread per cell ----
        if (tid < TILE) {
            cell_box_math(sp + tid * PRED_C + 80, st + tid * TGT_C + 80, aC, aO, aN);
        }

        MBAR_ARRIVE(empty_a[b]);

        // ---- producer: refill this buffer for tile it+2 ----
        if (tid == 0) {
            int ti = it + 2;
            if (ti < nmine) {
                MBAR_WAIT_PARITY(empty_a[b], ph);   // consumption #(it/2+1) done
                int tl = blockIdx.x + ti * gridDim.x;
                MBAR_EXPECT_TX(full_a[b], TILE_BYTES);
                BULK_G2S(smem_u32(spb[b]), P + (size_t)tl * SP_FLOATS, SP_BYTES, full_a[b]);
                BULK_G2S(smem_u32(stb[b]), T + (size_t)tl * ST_FLOATS, ST_BYTES, full_a[b]);
            }
        }
    }

    // ---- remainder cells (not taken for 401408): block 0, direct global ----
    if (rem > 0 && blockIdx.x == 0 && tid < rem) {
        int cell = ntiles * TILE + tid;
        const float* p = P + (size_t)cell * PRED_C;
        const float* t = T + (size_t)cell * TGT_C;
        float obj = t[80];
        for (int k = 0; k < 80; k++) {
            float d = fmaf(p[k], obj, -t[k]);
            aL = fmaf(d, d, aL);
        }
        float pb[10], tb[5];
        #pragma unroll
        for (int k = 0; k < 10; k++) pb[k] = p[80 + k];
        #pragma unroll
        for (int k = 0; k < 5; k++)  tb[k] = t[80 + k];
        cell_box_math(pb, tb, aC, aO, aN);
    }

    // ---- Block reduction ----
    #pragma unroll
    for (int off = 16; off > 0; off >>= 1) {
        aC += __shfl_xor_sync(FULL, aC, off);
        aO += __shfl_xor_sync(FULL, aO, off);
        aN += __shfl_xor_sync(FULL, aN, off);
        aL += __shfl_xor_sync(FULL, aL, off);
    }
    if (lane == 0) {
        red[0][wrp] = aC; red[1][wrp] = aO; red[2][wrp] = aN; red[3][wrp] = aL;
    }
    __syncthreads();
    if (tid == 0) {
        float s0 = 0, s1 = 0, s2 = 0, s3 = 0;
        #pragma unroll
        for (int w = 0; w < WARPS; w++) {
            s0 += red[0][w]; s1 += red[1][w]; s2 += red[2][w]; s3 += red[3][w];
        }
        g_partials[blockIdx.x * 4 + 0] = s0;
        g_partials[blockIdx.x * 4 + 1] = s1;
        g_partials[blockIdx.x * 4 + 2] = s2;
        g_partials[blockIdx.x * 4 + 3] = s3;
        __threadfence();
        unsigned prev = atomicAdd(&g_count, 1u);
        s_last = (prev == gridDim.x - 1) ? 1 : 0;
    }
    __syncthreads();

    // ---- Last block finalizes & resets counter for graph replay ----
    if (s_last) {
        double v0 = 0, v1 = 0, v2 = 0, v3 = 0;
        for (int b = tid; b < (int)gridDim.x; b += THREADS) {
            v0 += (double)__ldcg(&g_partials[b * 4 + 0]);
            v1 += (double)__ldcg(&g_partials[b * 4 + 1]);
            v2 += (double)__ldcg(&g_partials[b * 4 + 2]);
            v3 += (double)__ldcg(&g_partials[b * 4 + 3]);
        }
        #pragma unroll
        for (int off = 16; off > 0; off >>= 1) {
            v0 += __shfl_xor_sync(FULL, v0, off);
            v1 += __shfl_xor_sync(FULL, v1, off);
            v2 += __shfl_xor_sync(FULL, v2, off);
            v3 += __shfl_xor_sync(FULL, v3, off);
        }
        if (lane == 0) {
            dred[0][wrp] = v0; dred[1][wrp] = v1; dred[2][wrp] = v2; dred[3][wrp] = v3;
        }
        __syncthreads();
        if (tid == 0) {
            double c = 0, o = 0, n = 0, cl = 0;
            #pragma unroll
            for (int w = 0; w < WARPS; w++) {
                c += dred[0][w]; o += dred[1][w]; n += dred[2][w]; cl += dred[3][w];
            }
            out[0] = (float)(c * 5.0);   // coords (LAMBDA_COORDS)
            out[1] = (float)o;           // obj
            out[2] = (float)(n * 0.5);   // noobj (LAMBDA_NOOBJ)
            out[3] = (float)cl;          // classes
            atomicExch(&g_count, 0u);    // reset for next graph replay
        }
    }
}

extern "C" void kernel_launch(void* const* d_in, const int* in_sizes, int n_in,
                              void* d_out, int out_size) {
    const float* P = (const float*)d_in[0];   // predictions
    const float* T = (const float*)d_in[1];   // target
    float* out = (float*)d_out;

    int ncells = in_sizes[0] / PRED_C;        // 8192*7*7 = 401408

    cudaFuncSetAttribute(yolo_loss_tma,
                         cudaFuncAttributeMaxDynamicSharedMemorySize, DYN_SMEM);
    yolo_loss_tma<<<NBLOCKS, THREADS, DYN_SMEM>>>(P, T, out, ncells);
}